// round 4
// baseline (speedup 1.0000x reference)
#include <cuda_runtime.h>

#define NT 512

// Problem constants: B=256, T=16, O=32, E=32, I=32, H=HL=64, TE=512, EI=64, P=496

struct Params {
    const float* z;
    const float *ee1_w,*ee1_b,*ee2_w,*ee2_b,*ee3_w,*ee3_b;
    const float *ne1_w,*ne1_b,*ne2_w,*ne2_b,*ne3_w,*ne3_b,*ne4_w,*ne4_b;
    const float *le1_w,*le1_b,*le2_w,*le2_b,*le3_w,*le3_b;
    const float *lt1_w,*lt1_b,*lt2_w,*lt2_b,*lt3_w,*lt3_b,*lt4_w,*lt4_b,*lt5_w,*lt5_b;
    float* out;
    int t_future;
};

__device__ __forceinline__ void fma4(float acc[4], float a, const float4& w) {
    acc[0] = fmaf(a, w.x, acc[0]);
    acc[1] = fmaf(a, w.y, acc[1]);
    acc[2] = fmaf(a, w.z, acc[2]);
    acc[3] = fmaf(a, w.w, acc[3]);
}

// out[32][64] (optionally +=) = in[32][IN] @ W[IN][64] (+bias) (optional relu)
// 512 threads: 1 row x 4 cols per thread.
template<int IN, bool ACC, bool RELU>
__device__ __forceinline__ void layer32x64(const float* __restrict__ in,
                                           const float* __restrict__ W,
                                           const float* __restrict__ bias,
                                           float* __restrict__ out, int tid)
{
    const int c0 = (tid & 15) * 4;
    const int r  = tid >> 4;           // 0..31
    float acc[4];
    if (ACC) {
#pragma unroll
        for (int j = 0; j < 4; j++) acc[j] = out[r * 64 + c0 + j];
    } else {
#pragma unroll
        for (int j = 0; j < 4; j++) acc[j] = bias ? bias[c0 + j] : 0.f;
    }
    const float* in0 = in + r * IN;
#pragma unroll 4
    for (int k = 0; k < IN; k += 4) {
        float4 a = *(const float4*)(in0 + k);
        float4 w0 = *(const float4*)(W + (k + 0) * 64 + c0);
        float4 w1 = *(const float4*)(W + (k + 1) * 64 + c0);
        float4 w2 = *(const float4*)(W + (k + 2) * 64 + c0);
        float4 w3 = *(const float4*)(W + (k + 3) * 64 + c0);
        fma4(acc, a.x, w0); fma4(acc, a.y, w1); fma4(acc, a.z, w2); fma4(acc, a.w, w3);
    }
#pragma unroll
    for (int j = 0; j < 4; j++) {
        float v = acc[j];
        if (RELU) v = fmaxf(v, 0.f);
        out[r * 64 + c0 + j] = v;
    }
}

#define H2S 68   // padded stride for h2

// h2[128][H2S] = relu(h1[128][64] @ W[64][64] + bias). h1 smem, W/bias global.
// 512 threads: 4 rows x 4 cols per thread.
__device__ __forceinline__ void gemm128(const float* __restrict__ A,
                                        const float* __restrict__ Wg,
                                        const float* __restrict__ bias,
                                        float* __restrict__ Cout, int tid)
{
    const int c0 = (tid & 15) * 4;
    const int r0 = (tid >> 4) * 4;     // 0..124
    float acc[4][4];
#pragma unroll
    for (int i = 0; i < 4; i++)
#pragma unroll
        for (int j = 0; j < 4; j++) acc[i][j] = bias[c0 + j];
#pragma unroll 2
    for (int k = 0; k < 64; k += 4) {
        float4 w0 = *(const float4*)(Wg + (k + 0) * 64 + c0);
        float4 w1 = *(const float4*)(Wg + (k + 1) * 64 + c0);
        float4 w2 = *(const float4*)(Wg + (k + 2) * 64 + c0);
        float4 w3 = *(const float4*)(Wg + (k + 3) * 64 + c0);
#pragma unroll
        for (int i = 0; i < 4; i++) {
            float4 a = *(const float4*)(A + (r0 + i) * 64 + k);
            fma4(acc[i], a.x, w0); fma4(acc[i], a.y, w1);
            fma4(acc[i], a.z, w2); fma4(acc[i], a.w, w3);
        }
    }
#pragma unroll
    for (int i = 0; i < 4; i++)
#pragma unroll
        for (int j = 0; j < 4; j++)
            Cout[(r0 + i) * H2S + c0 + j] = fmaxf(acc[i][j], 0.f);
}

// agg[32][64] = G[32][64] @ W3[64][64] + (31-2r)*b3. G smem, W3/b3 global.
__device__ __forceinline__ void aggGemm(const float* __restrict__ G,
                                        const float* __restrict__ W3,
                                        const float* __restrict__ b3,
                                        float* __restrict__ agg, int tid)
{
    const int c0 = (tid & 15) * 4;
    const int r  = tid >> 4;
    const float sc = (float)(31 - 2 * r);
    float acc[4];
#pragma unroll
    for (int j = 0; j < 4; j++) acc[j] = sc * b3[c0 + j];
    const float* g0 = G + r * 64;
#pragma unroll 4
    for (int k = 0; k < 64; k += 4) {
        float4 a = *(const float4*)(g0 + k);
        float4 w0 = *(const float4*)(W3 + (k + 0) * 64 + c0);
        float4 w1 = *(const float4*)(W3 + (k + 1) * 64 + c0);
        float4 w2 = *(const float4*)(W3 + (k + 2) * 64 + c0);
        float4 w3 = *(const float4*)(W3 + (k + 3) * 64 + c0);
        fma4(acc, a.x, w0); fma4(acc, a.y, w1); fma4(acc, a.z, w2); fma4(acc, a.w, w3);
    }
#pragma unroll
    for (int j = 0; j < 4; j++) agg[r * 64 + c0 + j] = acc[j];
}

// small generic layer: out[32][OUT] = relu?(in[32][IN] @ W + b)
__device__ __forceinline__ void layer_small(const float* __restrict__ in, int IN,
                                            const float* __restrict__ W,
                                            const float* __restrict__ bias,
                                            float* __restrict__ out, int OUT,
                                            bool relu, int tid)
{
    for (int idx = tid; idx < 32 * OUT; idx += NT) {
        int r = idx / OUT, c = idx % OUT;
        float acc = bias[c];
        const float* inr = in + r * IN;
#pragma unroll 4
        for (int k = 0; k < IN; k++) acc = fmaf(inr[k], W[k * OUT + c], acc);
        out[idx] = relu ? fmaxf(acc, 0.f) : acc;
    }
}

// accumulate acc[4] += srcRow[64] @ Wg[64][64] slice (1 row x 4 cols)
__device__ __forceinline__ void acc1row(const float* __restrict__ srcRow,
                                        const float* __restrict__ Wg,
                                        float acc[4], int c0)
{
#pragma unroll 4
    for (int k = 0; k < 64; k += 4) {
        float4 a = *(const float4*)(srcRow + k);
        float4 w0 = *(const float4*)(Wg + (k + 0) * 64 + c0);
        float4 w1 = *(const float4*)(Wg + (k + 1) * 64 + c0);
        float4 w2 = *(const float4*)(Wg + (k + 2) * 64 + c0);
        float4 w3 = *(const float4*)(Wg + (k + 3) * 64 + c0);
        fma4(acc, a.x, w0); fma4(acc, a.y, w1); fma4(acc, a.z, w2); fma4(acc, a.w, w3);
    }
}

// edge block: ya/yb[32][64] smem -> agg[32][64]. Weights from global.
// 4 iterations of 128-pair windows; sparse signed scatter in registers.
__device__ __forceinline__ void edge_block(const float* ya, const float* yb,
                                           const float* __restrict__ b1,
                                           const float* __restrict__ W2g, const float* __restrict__ b2,
                                           const float* __restrict__ W3g, const float* __restrict__ b3,
                                           float* h1, float* h2, float* Gs, float* agg,
                                           const unsigned char* ii, const unsigned char* jj,
                                           const unsigned short* jl,
                                           int tid)
{
    const int n   = tid >> 4;          // 0..31
    const int c0s = (tid & 15) * 4;
    const int rs    = n * 31 - ((n * (n - 1)) >> 1);  // first pair with ii==n
    const int iiend = rs + 31 - n;
    float g[4] = {0.f, 0.f, 0.f, 0.f};
    int kcur = 0;

#pragma unroll 1
    for (int ch = 0; ch < 4; ch++) {
        const int p0 = ch * 128;
        // h1 = relu(ya[ii] + yb[jj] + b1) for this 128-pair window
        for (int idx = tid; idx < 128 * 64; idx += NT) {
            int pl = idx >> 6, c = idx & 63;
            int p = p0 + pl;
            float v = ya[ii[p] * 64 + c] + yb[jj[p] * 64 + c] + b1[c];
            h1[idx] = fmaxf(v, 0.f);
        }
        __syncthreads();
        gemm128(h1, W2g, b2, h2, tid);
        __syncthreads();
        // signed sparse scatter into register G
        int lo = max(rs, p0), hi = min(iiend, p0 + 128);
        for (int p = lo; p < hi; p++) {
            float4 v = *(const float4*)(h2 + (p - p0) * H2S + c0s);
            g[0] += v.x; g[1] += v.y; g[2] += v.z; g[3] += v.w;
        }
        while (kcur < n) {
            int p = jl[(n << 5) + kcur];
            if (p >= p0 + 128) break;
            float4 v = *(const float4*)(h2 + (p - p0) * H2S + c0s);
            g[0] -= v.x; g[1] -= v.y; g[2] -= v.z; g[3] -= v.w;
            kcur++;
        }
    }
#pragma unroll
    for (int j = 0; j < 4; j++) Gs[n * 64 + c0s + j] = g[j];
    __syncthreads();
    aggGemm(Gs, W3g, b3, agg, tid);
    __syncthreads();
}

// smem layout (float offsets)
#define OFF_H1   0       // 128*64
#define OFF_H2   8192    // 128*68
#define OFF_YA   16896   // 32*64
#define OFF_YB   18944
#define OFF_AGG  20992
#define OFF_ZC   23040
#define SMEM_FLOATS 25088
#define SMEM_BYTES  (SMEM_FLOATS * 4 + 2048 + 1024)  // + jl(u16 x1024) + ii/jj

__global__ void __launch_bounds__(NT, 2)
RelationalLatentDynamics_82849919140105_kernel(Params P)
{
    extern __shared__ float sm[];
    float* s_h1  = sm + OFF_H1;
    float* s_h2  = sm + OFF_H2;
    float* s_ya  = sm + OFF_YA;
    float* s_yb  = sm + OFF_YB;
    float* s_agg = sm + OFF_AGG;
    float* s_zc  = sm + OFF_ZC;
    unsigned short* s_jl = (unsigned short*)(sm + SMEM_FLOATS);
    unsigned char*  s_ii = (unsigned char*)(s_jl + 1024);
    unsigned char*  s_jj = s_ii + 512;

    const int tid = threadIdx.x;
    const int b = blockIdx.x;
    const int c0 = (tid & 15) * 4;
    const int r  = tid >> 4;

    // pair index tables (padded to 512)
    for (int p = tid; p < 512; p += NT) {
        if (p < 496) {
            int pp = p, i = 0;
            while (pp >= 31 - i) { pp -= 31 - i; i++; }
            s_ii[p] = (unsigned char)i;
            s_jj[p] = (unsigned char)(i + 1 + pp);
        } else {
            s_ii[p] = 0; s_jj[p] = 1;
        }
    }
    // jl[n][k] = index of pair (k, n) for k < n (ascending in k)
    for (int idx = tid; idx < 1024; idx += NT) {
        int n = idx >> 5, k = idx & 31;
        s_jl[idx] = (k < n)
            ? (unsigned short)(k * 31 - ((k * (k - 1)) >> 1) + (n - k - 1))
            : (unsigned short)0xFFFF;
    }

    const float* zb = P.z + (size_t)b * (16 * 32 * 32);

    // ---- Phase A: ya/yb = src @ ee1_w (streamed src chunks, register acc) ----
    {
        float accA[4] = {0,0,0,0}, accB[4] = {0,0,0,0};
#pragma unroll 1
        for (int ch = 0; ch < 8; ch++) {
            for (int idx = tid; idx < 2048; idx += NT) {
                int o = idx >> 6, fl = idx & 63;
                int t = 2 * ch + (fl >> 5), e = fl & 31;
                float v = zb[(t * 32 + o) * 32 + e];
                if (t > 0) v -= zb[((t - 1) * 32 + o) * 32 + e];
                s_h1[o * 64 + fl] = v;
            }
            __syncthreads();
            acc1row(s_h1 + r * 64, P.ee1_w + ch * 4096, accA, c0);
            acc1row(s_h1 + r * 64, P.ee1_w + 512 * 64 + ch * 4096, accB, c0);
            __syncthreads();
        }
#pragma unroll
        for (int j = 0; j < 4; j++) {
            s_ya[r * 64 + c0 + j] = accA[j];
            s_yb[r * 64 + c0 + j] = accB[j];
        }
    }
    __syncthreads();

    // ---- ee edge block ----
    edge_block(s_ya, s_yb, P.ee1_b, P.ee2_w, P.ee2_b, P.ee3_w, P.ee3_b,
               s_h1, s_h2, s_yb, s_agg, s_ii, s_jj, s_jl, tid);

    // ---- ne MLP ----
    layer32x64<64, false, false>(s_agg, P.ne1_w + 512 * 64, P.ne1_b, s_ya, tid);
    {
        float acc[4];
#pragma unroll
        for (int j = 0; j < 4; j++) acc[j] = s_ya[r * 64 + c0 + j];  // own cells
#pragma unroll 1
        for (int ch = 0; ch < 8; ch++) {
            for (int idx = tid; idx < 2048; idx += NT) {
                int o = idx >> 6, fl = idx & 63;
                int t = 2 * ch + (fl >> 5), e = fl & 31;
                float v = zb[(t * 32 + o) * 32 + e];
                if (t > 0) v -= zb[((t - 1) * 32 + o) * 32 + e];
                s_h1[o * 64 + fl] = v;
            }
            __syncthreads();
            acc1row(s_h1 + r * 64, P.ne1_w + ch * 4096, acc, c0);
            __syncthreads();
        }
#pragma unroll
        for (int j = 0; j < 4; j++)
            s_ya[r * 64 + c0 + j] = fmaxf(acc[j], 0.f);
    }
    __syncthreads();
    layer32x64<64, false, true>(s_ya, P.ne2_w, P.ne2_b, s_h1, tid);
    __syncthreads();
    layer_small(s_h1, 64, P.ne3_w, P.ne3_b, s_h2, 32, true, tid);
    __syncthreads();
    layer_small(s_h2, 32, P.ne4_w, P.ne4_b, s_h1, 32, false, tid);  // z_impl
    __syncthreads();

    // zc = concat(z[b,-1], z_impl)
    const float* zlast = zb + 15 * 32 * 32;
    for (int idx = tid; idx < 2048; idx += NT) {
        int o = idx >> 6, c = idx & 63;
        s_zc[idx] = (c < 32) ? zlast[o * 32 + c] : s_h1[o * 32 + (c - 32)];
    }
    __syncthreads();

    // ---- rollout ----
    float* outb = P.out + (size_t)b * (P.t_future * 32 * 32);
#pragma unroll 1
    for (int t = 0; t < P.t_future; t++) {
        layer32x64<64, false, false>(s_zc, P.le1_w,           nullptr, s_ya, tid);
        layer32x64<64, false, false>(s_zc, P.le1_w + 64 * 64, nullptr, s_yb, tid);
        __syncthreads();
        edge_block(s_ya, s_yb, P.le1_b, P.le2_w, P.le2_b, P.le3_w, P.le3_b,
                   s_h1, s_h2, s_yb, s_agg, s_ii, s_jj, s_jl, tid);

        layer32x64<64, false, false>(s_zc,  P.lt1_w,           P.lt1_b, s_h1, tid);
        layer32x64<64, true,  true >(s_agg, P.lt1_w + 64 * 64, nullptr, s_h1, tid);
        __syncthreads();
        layer32x64<64, false, true>(s_h1, P.lt2_w, P.lt2_b, s_h2, tid);
        __syncthreads();
        layer_small(s_h2, 64, P.lt3_w, P.lt3_b, s_h1, 32, true, tid);
        __syncthreads();
        layer_small(s_h1, 32, P.lt4_w, P.lt4_b, s_h2, 16, true, tid);
        __syncthreads();
        layer32x64<16, false, false>(s_h2, P.lt5_w, P.lt5_b, s_h1, tid);  // delta
        __syncthreads();

        for (int idx = tid; idx < 2048; idx += NT) {
            float zn = s_zc[idx] + s_h1[idx];
            s_zc[idx] = zn;
            int o = idx >> 6, c = idx & 63;
            if (c < 32) outb[t * 1024 + o * 32 + c] = zn;
        }
        __syncthreads();
    }
}

extern "C" void kernel_launch(void* const* d_in, const int* in_sizes, int n_in,
                              void* d_out, int out_size)
{
    Params P;
    int i = 0;
    P.z     = (const float*)d_in[i++];
    P.ee1_w = (const float*)d_in[i++]; P.ee1_b = (const float*)d_in[i++];
    P.ee2_w = (const float*)d_in[i++]; P.ee2_b = (const float*)d_in[i++];
    P.ee3_w = (const float*)d_in[i++]; P.ee3_b = (const float*)d_in[i++];
    P.ne1_w = (const float*)d_in[i++]; P.ne1_b = (const float*)d_in[i++];
    P.ne2_w = (const float*)d_in[i++]; P.ne2_b = (const float*)d_in[i++];
    P.ne3_w = (const float*)d_in[i++]; P.ne3_b = (const float*)d_in[i++];
    P.ne4_w = (const float*)d_in[i++]; P.ne4_b = (const float*)d_in[i++];
    P.le1_w = (const float*)d_in[i++]; P.le1_b = (const float*)d_in[i++];
    P.le2_w = (const float*)d_in[i++]; P.le2_b = (const float*)d_in[i++];
    P.le3_w = (const float*)d_in[i++]; P.le3_b = (const float*)d_in[i++];
    P.lt1_w = (const float*)d_in[i++]; P.lt1_b = (const float*)d_in[i++];
    P.lt2_w = (const float*)d_in[i++]; P.lt2_b = (const float*)d_in[i++];
    P.lt3_w = (const float*)d_in[i++]; P.lt3_b = (const float*)d_in[i++];
    P.lt4_w = (const float*)d_in[i++]; P.lt4_b = (const float*)d_in[i++];
    P.lt5_w = (const float*)d_in[i++]; P.lt5_b = (const float*)d_in[i++];
    P.out = (float*)d_out;
    P.t_future = out_size / (256 * 32 * 32);

    cudaFuncSetAttribute(RelationalLatentDynamics_82849919140105_kernel,
                         cudaFuncAttributeMaxDynamicSharedMemorySize, SMEM_BYTES);
    RelationalLatentDynamics_82849919140105_kernel<<<256, NT, SMEM_BYTES>>>(P);
}

// round 5
// speedup vs baseline: 1.1275x; 1.1275x over previous
#include <cuda_runtime.h>

#define NT 256

// Problem constants: B=256, T=16, O=32, E=32, I=32, H=HL=64, TE=512, EI=64, P=496

struct Params {
    const float* z;
    const float *ee1_w,*ee1_b,*ee2_w,*ee2_b,*ee3_w,*ee3_b;
    const float *ne1_w,*ne1_b,*ne2_w,*ne2_b,*ne3_w,*ne3_b,*ne4_w,*ne4_b;
    const float *le1_w,*le1_b,*le2_w,*le2_b,*le3_w,*le3_b;
    const float *lt1_w,*lt1_b,*lt2_w,*lt2_b,*lt3_w,*lt3_b,*lt4_w,*lt4_b,*lt5_w,*lt5_b;
    float* out;
    int t_future;
};

__device__ __forceinline__ void fma4(float acc[4], float a, const float4& w) {
    acc[0] = fmaf(a, w.x, acc[0]);
    acc[1] = fmaf(a, w.y, acc[1]);
    acc[2] = fmaf(a, w.z, acc[2]);
    acc[3] = fmaf(a, w.w, acc[3]);
}

// out[32][64] (optionally +=) = in[32][IN] @ W[IN][64] (+bias) (optional relu)
// 256 threads: 2 rows x 4 cols per thread.
template<int IN, bool ACC, bool RELU>
__device__ __forceinline__ void layer32x64(const float* __restrict__ in,
                                           const float* __restrict__ W,
                                           const float* __restrict__ bias,
                                           float* __restrict__ out, int tid)
{
    const int c0 = (tid & 15) * 4;
    const int r0 = (tid >> 4) * 2;
    float acc0[4], acc1[4];
    if (ACC) {
#pragma unroll
        for (int j = 0; j < 4; j++) {
            acc0[j] = out[r0 * 64 + c0 + j];
            acc1[j] = out[(r0 + 1) * 64 + c0 + j];
        }
    } else {
#pragma unroll
        for (int j = 0; j < 4; j++) {
            float bv = bias ? bias[c0 + j] : 0.f;
            acc0[j] = bv; acc1[j] = bv;
        }
    }
    const float* in0 = in + r0 * IN;
    const float* in1 = in0 + IN;
#pragma unroll 4
    for (int k = 0; k < IN; k += 4) {
        float4 a0 = *(const float4*)(in0 + k);
        float4 a1 = *(const float4*)(in1 + k);
        float4 w0 = *(const float4*)(W + (k + 0) * 64 + c0);
        float4 w1 = *(const float4*)(W + (k + 1) * 64 + c0);
        float4 w2 = *(const float4*)(W + (k + 2) * 64 + c0);
        float4 w3 = *(const float4*)(W + (k + 3) * 64 + c0);
        fma4(acc0, a0.x, w0); fma4(acc0, a0.y, w1); fma4(acc0, a0.z, w2); fma4(acc0, a0.w, w3);
        fma4(acc1, a1.x, w0); fma4(acc1, a1.y, w1); fma4(acc1, a1.z, w2); fma4(acc1, a1.w, w3);
    }
#pragma unroll
    for (int j = 0; j < 4; j++) {
        float v0 = acc0[j], v1 = acc1[j];
        if (RELU) { v0 = fmaxf(v0, 0.f); v1 = fmaxf(v1, 0.f); }
        out[r0 * 64 + c0 + j] = v0;
        out[(r0 + 1) * 64 + c0 + j] = v1;
    }
}

#define H2S 68   // padded stride for h2 (16B-aligned, bank-conflict-free scatter)

// h2[128][H2S] = relu(h1[128][64] @ W[64][64] + bias). h1 smem, W/bias global (L1).
// 256 threads: 8 rows x 4 cols per thread.
__device__ __forceinline__ void gemm128(const float* __restrict__ A,
                                        const float* __restrict__ Wg,
                                        const float* __restrict__ bias,
                                        float* __restrict__ Cout, int tid)
{
    const int c0 = (tid & 15) * 4;
    const int r0 = (tid >> 4) * 8;     // 0..120
    float acc[8][4];
    float bv[4];
#pragma unroll
    for (int j = 0; j < 4; j++) bv[j] = bias[c0 + j];
#pragma unroll
    for (int i = 0; i < 8; i++)
#pragma unroll
        for (int j = 0; j < 4; j++) acc[i][j] = bv[j];
#pragma unroll 2
    for (int k = 0; k < 64; k += 4) {
        float4 w0 = *(const float4*)(Wg + (k + 0) * 64 + c0);
        float4 w1 = *(const float4*)(Wg + (k + 1) * 64 + c0);
        float4 w2 = *(const float4*)(Wg + (k + 2) * 64 + c0);
        float4 w3 = *(const float4*)(Wg + (k + 3) * 64 + c0);
#pragma unroll
        for (int i = 0; i < 8; i++) {
            float4 a = *(const float4*)(A + (r0 + i) * 64 + k);
            fma4(acc[i], a.x, w0); fma4(acc[i], a.y, w1);
            fma4(acc[i], a.z, w2); fma4(acc[i], a.w, w3);
        }
    }
#pragma unroll
    for (int i = 0; i < 8; i++)
#pragma unroll
        for (int j = 0; j < 4; j++)
            Cout[(r0 + i) * H2S + c0 + j] = fmaxf(acc[i][j], 0.f);
}

// agg[32][64] = G[32][64] @ W3[64][64] + (31-2n)*b3   (scatter bias correction)
__device__ __forceinline__ void aggGemm(const float* __restrict__ G,
                                        const float* __restrict__ W3,
                                        const float* __restrict__ b3,
                                        float* __restrict__ agg, int tid)
{
    const int c0 = (tid & 15) * 4;
    const int r0 = (tid >> 4) * 2;
    const float sc0 = (float)(31 - 2 * r0);
    const float sc1 = (float)(31 - 2 * (r0 + 1));
    float acc0[4], acc1[4];
#pragma unroll
    for (int j = 0; j < 4; j++) {
        float bvv = b3[c0 + j];
        acc0[j] = sc0 * bvv; acc1[j] = sc1 * bvv;
    }
    const float* g0 = G + r0 * 64;
    const float* g1 = g0 + 64;
#pragma unroll 4
    for (int k = 0; k < 64; k += 4) {
        float4 a0 = *(const float4*)(g0 + k);
        float4 a1 = *(const float4*)(g1 + k);
        float4 w0 = *(const float4*)(W3 + (k + 0) * 64 + c0);
        float4 w1 = *(const float4*)(W3 + (k + 1) * 64 + c0);
        float4 w2 = *(const float4*)(W3 + (k + 2) * 64 + c0);
        float4 w3 = *(const float4*)(W3 + (k + 3) * 64 + c0);
        fma4(acc0, a0.x, w0); fma4(acc0, a0.y, w1); fma4(acc0, a0.z, w2); fma4(acc0, a0.w, w3);
        fma4(acc1, a1.x, w0); fma4(acc1, a1.y, w1); fma4(acc1, a1.z, w2); fma4(acc1, a1.w, w3);
    }
#pragma unroll
    for (int j = 0; j < 4; j++) {
        agg[r0 * 64 + c0 + j] = acc0[j];
        agg[(r0 + 1) * 64 + c0 + j] = acc1[j];
    }
}

// small generic layer: out[32][OUT] = relu?(in[32][IN] @ W + b)
__device__ __forceinline__ void layer_small(const float* __restrict__ in, int IN,
                                            const float* __restrict__ W,
                                            const float* __restrict__ bias,
                                            float* __restrict__ out, int OUT,
                                            bool relu, int tid)
{
    for (int idx = tid; idx < 32 * OUT; idx += NT) {
        int r = idx / OUT, c = idx % OUT;
        float acc = bias[c];
        const float* inr = in + r * IN;
#pragma unroll 4
        for (int k = 0; k < IN; k++) acc = fmaf(inr[k], W[k * OUT + c], acc);
        out[idx] = relu ? fmaxf(acc, 0.f) : acc;
    }
}

// accumulate one 64-k chunk: acc[2][4] += src[32][64] @ Wg[64][64] (Wg global)
__device__ __forceinline__ void acc_chunk(const float* __restrict__ src,
                                          const float* __restrict__ Wg,
                                          float acc0[4], float acc1[4],
                                          int r0, int c0)
{
    const float* in0 = src + r0 * 64;
    const float* in1 = in0 + 64;
#pragma unroll 4
    for (int k = 0; k < 64; k += 4) {
        float4 a0 = *(const float4*)(in0 + k);
        float4 a1 = *(const float4*)(in1 + k);
        float4 w0 = *(const float4*)(Wg + (k + 0) * 64 + c0);
        float4 w1 = *(const float4*)(Wg + (k + 1) * 64 + c0);
        float4 w2 = *(const float4*)(Wg + (k + 2) * 64 + c0);
        float4 w3 = *(const float4*)(Wg + (k + 3) * 64 + c0);
        fma4(acc0, a0.x, w0); fma4(acc0, a0.y, w1); fma4(acc0, a0.z, w2); fma4(acc0, a0.w, w3);
        fma4(acc1, a1.x, w0); fma4(acc1, a1.y, w1); fma4(acc1, a1.z, w2); fma4(acc1, a1.w, w3);
    }
}

// edge block: ya/yb[32][64] smem -> agg[32][64]. W2/W3 from global (L1-resident).
// 4 windows of 128 pairs; sparse signed scatter in registers (8 cols/thread).
__device__ __forceinline__ void edge_block(const float* ya, const float* yb,
                                           const float* __restrict__ b1,
                                           const float* __restrict__ W2g, const float* __restrict__ b2,
                                           const float* __restrict__ W3g, const float* __restrict__ b3,
                                           float* h1, float* h2, float* Gs, float* agg,
                                           const unsigned char* ii, const unsigned char* jj,
                                           const unsigned short* jl,
                                           int tid)
{
    const int n   = tid >> 3;          // 0..31
    const int c0s = (tid & 7) * 8;
    const int rs    = n * 31 - ((n * (n - 1)) >> 1);  // first pair with ii==n
    const int iiend = rs + 31 - n;
    float g[8];
#pragma unroll
    for (int j = 0; j < 8; j++) g[j] = 0.f;
    int kcur = 0;

#pragma unroll 1
    for (int ch = 0; ch < 4; ch++) {
        const int p0 = ch * 128;
        // h1 = relu(ya[ii] + yb[jj] + b1) for this 128-pair window
        for (int idx = tid; idx < 128 * 64; idx += NT) {
            int pl = idx >> 6, c = idx & 63;
            int p = p0 + pl;
            float v = ya[ii[p] * 64 + c] + yb[jj[p] * 64 + c] + b1[c];
            h1[idx] = fmaxf(v, 0.f);
        }
        __syncthreads();
        gemm128(h1, W2g, b2, h2, tid);
        __syncthreads();
        // signed sparse scatter into register G
        int lo = max(rs, p0), hi = min(iiend, p0 + 128);
        for (int p = lo; p < hi; p++) {
            const float* r = h2 + (p - p0) * H2S + c0s;
            float4 v0 = *(const float4*)(r);
            float4 v1 = *(const float4*)(r + 4);
            g[0] += v0.x; g[1] += v0.y; g[2] += v0.z; g[3] += v0.w;
            g[4] += v1.x; g[5] += v1.y; g[6] += v1.z; g[7] += v1.w;
        }
        while (kcur < n) {
            int p = jl[(n << 5) + kcur];
            if (p >= p0 + 128) break;
            const float* r = h2 + (p - p0) * H2S + c0s;
            float4 v0 = *(const float4*)(r);
            float4 v1 = *(const float4*)(r + 4);
            g[0] -= v0.x; g[1] -= v0.y; g[2] -= v0.z; g[3] -= v0.w;
            g[4] -= v1.x; g[5] -= v1.y; g[6] -= v1.z; g[7] -= v1.w;
            kcur++;
        }
    }
#pragma unroll
    for (int j = 0; j < 8; j++) Gs[n * 64 + c0s + j] = g[j];
    __syncthreads();
    aggGemm(Gs, W3g, b3, agg, tid);
    __syncthreads();
}

// smem layout (float offsets)
#define OFF_H1   0       // 128*64
#define OFF_H2   8192    // 128*68
#define OFF_YA   16896   // 32*64
#define OFF_YB   18944
#define OFF_AGG  20992
#define OFF_ZC   23040
#define SMEM_FLOATS 25088
#define SMEM_BYTES  (SMEM_FLOATS * 4 + 2048 + 1024)  // + jl(u16 x1024) + ii/jj

__global__ void __launch_bounds__(NT, 2)
RelationalLatentDynamics_82849919140105_kernel(Params P)
{
    extern __shared__ float sm[];
    float* s_h1  = sm + OFF_H1;
    float* s_h2  = sm + OFF_H2;
    float* s_ya  = sm + OFF_YA;
    float* s_yb  = sm + OFF_YB;
    float* s_agg = sm + OFF_AGG;
    float* s_zc  = sm + OFF_ZC;
    unsigned short* s_jl = (unsigned short*)(sm + SMEM_FLOATS);
    unsigned char*  s_ii = (unsigned char*)(s_jl + 1024);
    unsigned char*  s_jj = s_ii + 512;

    const int tid = threadIdx.x;
    const int b = blockIdx.x;
    const int c0 = (tid & 15) * 4;
    const int r0 = (tid >> 4) * 2;

    // pair index tables (padded to 512)
    for (int p = tid; p < 512; p += NT) {
        if (p < 496) {
            int pp = p, i = 0;
            while (pp >= 31 - i) { pp -= 31 - i; i++; }
            s_ii[p] = (unsigned char)i;
            s_jj[p] = (unsigned char)(i + 1 + pp);
        } else {
            s_ii[p] = 0; s_jj[p] = 1;
        }
    }
    // jl[n][k] = index of pair (k, n) for k < n (ascending in k)
    for (int idx = tid; idx < 1024; idx += NT) {
        int n = idx >> 5, k = idx & 31;
        s_jl[idx] = (k < n)
            ? (unsigned short)(k * 31 - ((k * (k - 1)) >> 1) + (n - k - 1))
            : (unsigned short)0xFFFF;
    }

    const float* zb = P.z + (size_t)b * (16 * 32 * 32);

    // ---- Phase A: ya/yb = src @ ee1_w (streamed src chunks, register acc) ----
    {
        float accA0[4] = {0,0,0,0}, accA1[4] = {0,0,0,0};
        float accB0[4] = {0,0,0,0}, accB1[4] = {0,0,0,0};
#pragma unroll 1
        for (int ch = 0; ch < 8; ch++) {
            for (int idx = tid; idx < 2048; idx += NT) {
                int o = idx >> 6, fl = idx & 63;
                int t = 2 * ch + (fl >> 5), e = fl & 31;
                float v = zb[(t * 32 + o) * 32 + e];
                if (t > 0) v -= zb[((t - 1) * 32 + o) * 32 + e];
                s_h1[o * 64 + fl] = v;
            }
            __syncthreads();
            acc_chunk(s_h1, P.ee1_w + ch * 4096, accA0, accA1, r0, c0);
            acc_chunk(s_h1, P.ee1_w + 512 * 64 + ch * 4096, accB0, accB1, r0, c0);
            __syncthreads();
        }
#pragma unroll
        for (int j = 0; j < 4; j++) {
            s_ya[r0 * 64 + c0 + j] = accA0[j];
            s_ya[(r0 + 1) * 64 + c0 + j] = accA1[j];
            s_yb[r0 * 64 + c0 + j] = accB0[j];
            s_yb[(r0 + 1) * 64 + c0 + j] = accB1[j];
        }
    }
    __syncthreads();

    // ---- ee edge block ----
    edge_block(s_ya, s_yb, P.ee1_b, P.ee2_w, P.ee2_b, P.ee3_w, P.ee3_b,
               s_h1, s_h2, s_yb, s_agg, s_ii, s_jj, s_jl, tid);

    // ---- ne MLP ----
    layer32x64<64, false, false>(s_agg, P.ne1_w + 512 * 64, P.ne1_b, s_ya, tid);
    {
        float acc0[4], acc1[4];
#pragma unroll
        for (int j = 0; j < 4; j++) {
            acc0[j] = s_ya[r0 * 64 + c0 + j];           // own cells, no sync needed
            acc1[j] = s_ya[(r0 + 1) * 64 + c0 + j];
        }
#pragma unroll 1
        for (int ch = 0; ch < 8; ch++) {
            for (int idx = tid; idx < 2048; idx += NT) {
                int o = idx >> 6, fl = idx & 63;
                int t = 2 * ch + (fl >> 5), e = fl & 31;
                float v = zb[(t * 32 + o) * 32 + e];
                if (t > 0) v -= zb[((t - 1) * 32 + o) * 32 + e];
                s_h1[o * 64 + fl] = v;
            }
            __syncthreads();
            acc_chunk(s_h1, P.ne1_w + ch * 4096, acc0, acc1, r0, c0);
            __syncthreads();
        }
#pragma unroll
        for (int j = 0; j < 4; j++) {
            s_ya[r0 * 64 + c0 + j] = fmaxf(acc0[j], 0.f);
            s_ya[(r0 + 1) * 64 + c0 + j] = fmaxf(acc1[j], 0.f);
        }
    }
    __syncthreads();
    layer32x64<64, false, true>(s_ya, P.ne2_w, P.ne2_b, s_h1, tid);
    __syncthreads();
    layer_small(s_h1, 64, P.ne3_w, P.ne3_b, s_h2, 32, true, tid);
    __syncthreads();
    layer_small(s_h2, 32, P.ne4_w, P.ne4_b, s_h1, 32, false, tid);  // z_impl
    __syncthreads();

    // zc = concat(z[b,-1], z_impl)
    const float* zlast = zb + 15 * 32 * 32;
    for (int idx = tid; idx < 2048; idx += NT) {
        int o = idx >> 6, c = idx & 63;
        s_zc[idx] = (c < 32) ? zlast[o * 32 + c] : s_h1[o * 32 + (c - 32)];
    }
    __syncthreads();

    // ---- rollout ----
    float* outb = P.out + (size_t)b * (P.t_future * 32 * 32);
#pragma unroll 1
    for (int t = 0; t < P.t_future; t++) {
        layer32x64<64, false, false>(s_zc, P.le1_w,           nullptr, s_ya, tid);
        layer32x64<64, false, false>(s_zc, P.le1_w + 64 * 64, nullptr, s_yb, tid);
        __syncthreads();
        edge_block(s_ya, s_yb, P.le1_b, P.le2_w, P.le2_b, P.le3_w, P.le3_b,
                   s_h1, s_h2, s_yb, s_agg, s_ii, s_jj, s_jl, tid);

        layer32x64<64, false, false>(s_zc,  P.lt1_w,           P.lt1_b, s_h1, tid);
        layer32x64<64, true,  true >(s_agg, P.lt1_w + 64 * 64, nullptr, s_h1, tid);
        __syncthreads();
        layer32x64<64, false, true>(s_h1, P.lt2_w, P.lt2_b, s_h2, tid);
        __syncthreads();
        layer_small(s_h2, 64, P.lt3_w, P.lt3_b, s_h1, 32, true, tid);
        __syncthreads();
        layer_small(s_h1, 32, P.lt4_w, P.lt4_b, s_h2, 16, true, tid);
        __syncthreads();
        layer32x64<16, false, false>(s_h2, P.lt5_w, P.lt5_b, s_h1, tid);  // delta
        __syncthreads();

        for (int idx = tid; idx < 2048; idx += NT) {
            float zn = s_zc[idx] + s_h1[idx];
            s_zc[idx] = zn;
            int o = idx >> 6, c = idx & 63;
            if (c < 32) outb[t * 1024 + o * 32 + c] = zn;
        }
        __syncthreads();
    }
}

extern "C" void kernel_launch(void* const* d_in, const int* in_sizes, int n_in,
                              void* d_out, int out_size)
{
    Params P;
    int i = 0;
    P.z     = (const float*)d_in[i++];
    P.ee1_w = (const float*)d_in[i++]; P.ee1_b = (const float*)d_in[i++];
    P.ee2_w = (const float*)d_in[i++]; P.ee2_b = (const float*)d_in[i++];
    P.ee3_w = (const float*)d_in[i++]; P.ee3_b = (const float*)d_in[i++];
    P.ne1_w = (const float*)d_in[i++]; P.ne1_b = (const float*)d_in[i++];
    P.ne2_w = (const float*)d_in[i++]; P.ne2_b = (const float*)d_in[i++];
    P.ne3_w = (const float*)d_in[i++]; P.ne3_b = (const float*)d_in[i++];
    P.ne4_w = (const float*)d_in[i++]; P.ne4_b = (const float*)d_in[i++];
    P.le1_w = (const float*)d_in[i++]; P.le1_b = (const float*)d_in[i++];
    P.le2_w = (const float*)d_in[i++]; P.le2_b = (const float*)d_in[i++];
    P.le3_w = (const float*)d_in[i++]; P.le3_b = (const float*)d_in[i++];
    P.lt1_w = (const float*)d_in[i++]; P.lt1_b = (const float*)d_in[i++];
    P.lt2_w = (const float*)d_in[i++]; P.lt2_b = (const float*)d_in[i++];
    P.lt3_w = (const float*)d_in[i++]; P.lt3_b = (const float*)d_in[i++];
    P.lt4_w = (const float*)d_in[i++]; P.lt4_b = (const float*)d_in[i++];
    P.lt5_w = (const float*)d_in[i++]; P.lt5_b = (const float*)d_in[i++];
    P.out = (float*)d_out;
    P.t_future = out_size / (256 * 32 * 32);

    cudaFuncSetAttribute(RelationalLatentDynamics_82849919140105_kernel,
                         cudaFuncAttributeMaxDynamicSharedMemorySize, SMEM_BYTES);
    RelationalLatentDynamics_82849919140105_kernel<<<256, NT, SMEM_BYTES>>>(P);
}